// round 17
// baseline (speedup 1.0000x reference)
#include <cuda_runtime.h>
#include <cuda_bf16.h>
#include <cstdint>

#define NELEM 4194304          // 32*512*256 == 4*512*2048
#define PSZ   262144           // 512*512 (one U/V/M plane)

// ---------------------------------------------------------------------------
// device scratch
// ---------------------------------------------------------------------------
__device__ float g_saf[NELEM];           // conv_o input fp32 pixel-major [b][pix][ci]
__device__ __nv_bfloat16 g_Uh[144*PSZ];  // wino weights [conv*36+pos][co][ci]
__device__ __nv_bfloat16 g_Ul[144*PSZ];
__device__ __nv_bfloat16 g_Vh[108*PSZ];  // wino inputs  [plane][tile][ci]
__device__ __nv_bfloat16 g_Vl[108*PSZ];
__device__ float g_M[108*PSZ];           // GEMM out     [plane][co][tile]
__device__ float g_y2[NELEM];            // conv(v) output (32,512,256) fp32
__device__ __nv_bfloat16 g_Qh[NELEM], g_Ql[NELEM];   // [n][d][c], c=h*32+r
__device__ __nv_bfloat16 g_Kh[NELEM], g_Kl[NELEM];
__device__ __nv_bfloat16 g_Vth[NELEM], g_Vtl[NELEM]; // transposed: [n][c][dk]
__device__ __nv_bfloat16 g_ath[2*NELEM], g_atl[2*NELEM]; // attn hi/lo

// ---------------------------------------------------------------------------
// helpers
// ---------------------------------------------------------------------------
__device__ __forceinline__ uint32_t smem_u32(const void* p) {
    uint32_t a;
    asm("{ .reg .u64 t; cvta.to.shared.u64 t, %1; cvt.u32.u64 %0, t; }" : "=r"(a) : "l"(p));
    return a;
}
#define SWZ(o) ((o) ^ (((o) >> 3) & 0x70))
#define CPA(dst, src, sz) \
    asm volatile("cp.async.cg.shared.global [%0], [%1], 16, %2;" \
        :: "r"(dst), "l"(src), "r"(sz) : "memory")
#define LDM4(r, addr) \
    asm volatile("ldmatrix.sync.aligned.m8n8.x4.shared.b16 {%0,%1,%2,%3}, [%4];" \
        : "=r"((r)[0]), "=r"((r)[1]), "=r"((r)[2]), "=r"((r)[3]) : "r"(addr))
#define MMA_BF16(d, a, b0, b1) \
    asm volatile("mma.sync.aligned.m16n8k16.row.col.f32.bf16.bf16.f32 " \
        "{%0,%1,%2,%3}, {%4,%5,%6,%7}, {%8,%9}, {%0,%1,%2,%3};" \
        : "+f"((d)[0]), "+f"((d)[1]), "+f"((d)[2]), "+f"((d)[3]) \
        : "r"((a)[0]), "r"((a)[1]), "r"((a)[2]), "r"((a)[3]), "r"(b0), "r"(b1))
#define WAITP(addr, ph) do { \
    asm volatile("{\n\t.reg .pred P;\n\tWL%=:\n\t" \
        "mbarrier.try_wait.parity.acquire.cta.shared::cta.b64 P, [%0], %1, 0x989680;\n\t" \
        "@P bra.uni WD%=;\n\tbra.uni WL%=;\n\tWD%=:\n\t}" \
        :: "r"(addr), "r"(ph) : "memory"); \
} while (0)

#define STAGE 32768u
#define MBAR_BASE 98304u
#define SMEM_BYTES 98368
#define PROW(r) ((uint32_t)((((r) >> 1) << 7) | (((r) & 1) << 6)))

__device__ __forceinline__ void split2(float v0, float v1, uint32_t& hp, uint32_t& lp) {
    __nv_bfloat16 h0 = __float2bfloat16(v0);
    __nv_bfloat16 h1 = __float2bfloat16(v1);
    __nv_bfloat16 l0 = __float2bfloat16(v0 - __bfloat162float(h0));
    __nv_bfloat16 l1 = __float2bfloat16(v1 - __bfloat162float(h1));
    hp = (uint32_t)*(uint16_t*)&h0 | ((uint32_t)*(uint16_t*)&h1 << 16);
    lp = (uint32_t)*(uint16_t*)&l0 | ((uint32_t)*(uint16_t*)&l1 << 16);
}

// ---------------------------------------------------------------------------
// compute one K32 chunk, warp tile 64x32: D += Ah*Bh + Ah*Bl + Al*Bh
// ---------------------------------------------------------------------------
__device__ __forceinline__ void mma_compute32(uint32_t bs, uint32_t a_rowb,
                                              uint32_t b_rowb, float (&acc)[16][4])
{
#pragma unroll
    for (int s = 0; s < 2; ++s) {
        uint32_t ah[4][4], bb[2][4], blf[2][4];
#pragma unroll
        for (int i = 0; i < 4; ++i)
            LDM4(ah[i], bs + SWZ(a_rowb + i * 1024 + s * 32));
#pragma unroll
        for (int j = 0; j < 2; ++j)
            LDM4(bb[j], bs + 16384u + SWZ(b_rowb + j * 1024 + s * 32));
#pragma unroll
        for (int i = 0; i < 4; ++i)
#pragma unroll
            for (int jj = 0; jj < 4; ++jj)
                MMA_BF16(acc[i * 4 + jj], ah[i],
                         bb[jj >> 1][(jj & 1) * 2], bb[jj >> 1][(jj & 1) * 2 + 1]);
#pragma unroll
        for (int j = 0; j < 2; ++j)
            LDM4(blf[j], bs + 24576u + SWZ(b_rowb + j * 1024 + s * 32));
#pragma unroll
        for (int i = 0; i < 4; ++i)
#pragma unroll
            for (int jj = 0; jj < 4; ++jj)
                MMA_BF16(acc[i * 4 + jj], ah[i],
                         blf[jj >> 1][(jj & 1) * 2], blf[jj >> 1][(jj & 1) * 2 + 1]);
#pragma unroll
        for (int i = 0; i < 4; ++i)
            LDM4(ah[i], bs + 8192u + SWZ(a_rowb + i * 1024 + s * 32));
#pragma unroll
        for (int i = 0; i < 4; ++i)
#pragma unroll
            for (int jj = 0; jj < 4; ++jj)
                MMA_BF16(acc[i * 4 + jj], ah[i],
                         bb[jj >> 1][(jj & 1) * 2], bb[jj >> 1][(jj & 1) * 2 + 1]);
    }
}

// ---------------------------------------------------------------------------
// pipeline state shared by the GEMM bodies
// ---------------------------------------------------------------------------
struct PipeCtx {
    uint32_t sb, stb, a_rowb, b_rowb;
    const char *srcA_h, *srcA_l, *srcB_h, *srcB_l;
    int ps, pph, cs, cph;
};

__device__ __forceinline__ void pipe_init(PipeCtx& P, uint32_t sb, int tid,
    const __nv_bfloat16* Ah, const __nv_bfloat16* Al,
    const __nv_bfloat16* Bh, const __nv_bfloat16* Bl,
    int m0, int n0, int Kdim)
{
    int wid = tid >> 5, lane = tid & 31;
    int wm = wid & 1, wn = wid >> 1;
    int lr = tid >> 1, lh = tid & 1;
    P.sb = sb;
    P.stb = PROW(lr) + lh * 32u;
    P.srcA_h = (const char*)(Ah + (size_t)(m0 + lr) * Kdim + lh * 16);
    P.srcA_l = (const char*)(Al + (size_t)(m0 + lr) * Kdim + lh * 16);
    P.srcB_h = (const char*)(Bh + (size_t)(n0 + lr) * Kdim + lh * 16);
    P.srcB_l = (const char*)(Bl + (size_t)(n0 + lr) * Kdim + lh * 16);
    int arow = wm * 64 + (lane & 15);
    P.a_rowb = PROW(arow) + ((lane & 16) ? 16u : 0u);
    int brow = wn * 32 + (lane & 7) + ((lane & 16) ? 8 : 0);
    P.b_rowb = PROW(brow) + ((lane & 8) ? 16u : 0u);
    if (tid == 0) {
#pragma unroll
        for (int s = 0; s < 3; ++s) {
            asm volatile("mbarrier.init.shared.b64 [%0], %1;"
                         :: "r"(sb + MBAR_BASE + s * 16u), "r"(256) : "memory");
            asm volatile("mbarrier.init.shared.b64 [%0], %1;"
                         :: "r"(sb + MBAR_BASE + s * 16u + 8u), "r"(256) : "memory");
        }
    }
    __syncthreads();
    P.ps = 0; P.pph = 1; P.cs = 0; P.cph = 0;
}

__device__ __forceinline__ void pipe_produce(PipeCtx& P, int itn)
{
    uint32_t fmb = P.sb + MBAR_BASE + (uint32_t)P.ps * 16u;
    WAITP(fmb + 8u, P.pph);
    int cb = itn * 64;
    uint32_t bs = P.sb + (uint32_t)P.ps * STAGE;
    uint32_t s0 = SWZ(P.stb), s1 = SWZ(P.stb + 16u);
    CPA(bs + s0,          P.srcA_h + cb,      16u);
    CPA(bs + s1,          P.srcA_h + cb + 16, 16u);
    CPA(bs + 8192u + s0,  P.srcA_l + cb,      16u);
    CPA(bs + 8192u + s1,  P.srcA_l + cb + 16, 16u);
    CPA(bs + 16384u + s0, P.srcB_h + cb,      16u);
    CPA(bs + 16384u + s1, P.srcB_h + cb + 16, 16u);
    CPA(bs + 24576u + s0, P.srcB_l + cb,      16u);
    CPA(bs + 24576u + s1, P.srcB_l + cb + 16, 16u);
    asm volatile("cp.async.mbarrier.arrive.noinc.shared::cta.b64 [%0];"
                 :: "r"(fmb) : "memory");
    if (++P.ps == 3) { P.ps = 0; P.pph ^= 1; }
}

__device__ __forceinline__ void pipe_mainloop(PipeCtx& P, int nchunk, float (&acc)[16][4])
{
    pipe_produce(P, 0);
    pipe_produce(P, 1);
    for (int it = 0; it < nchunk; ++it) {
        if (it + 2 < nchunk) pipe_produce(P, it + 2);
        uint32_t fmb = P.sb + MBAR_BASE + (uint32_t)P.cs * 16u;
        WAITP(fmb, P.cph);
        mma_compute32(P.sb + (uint32_t)P.cs * STAGE, P.a_rowb, P.b_rowb, acc);
        asm volatile("mbarrier.arrive.shared::cta.b64 _, [%0];"
                     :: "r"(fmb + 8u) : "memory");
        if (++P.cs == 3) { P.cs = 0; P.cph ^= 1; }
    }
}

// ---------------------------------------------------------------------------
// mbarrier-pipelined GEMM with direct row-major epilogue
// ---------------------------------------------------------------------------
__device__ __forceinline__ void gemm_mb(
    const __nv_bfloat16* __restrict__ Ah, const __nv_bfloat16* __restrict__ Al,
    const __nv_bfloat16* __restrict__ Bh, const __nv_bfloat16* __restrict__ Bl,
    int Kdim, int nchunk, float* __restrict__ C, int ldc)
{
    extern __shared__ char smem[];
    uint32_t sb = smem_u32(smem);
    int tid = threadIdx.x, wid = tid >> 5, lane = tid & 31;
    int m0 = blockIdx.y * 128, n0 = blockIdx.x * 128;
    int wm = wid & 1, wn = wid >> 1;

    PipeCtx P;
    pipe_init(P, sb, tid, Ah, Al, Bh, Bl, m0, n0, Kdim);

    float acc[16][4];
#pragma unroll
    for (int i = 0; i < 16; ++i)
#pragma unroll
        for (int j = 0; j < 4; ++j) acc[i][j] = 0.f;

    pipe_mainloop(P, nchunk, acc);

#pragma unroll
    for (int i = 0; i < 4; ++i) {
        int row = m0 + wm * 64 + i * 16 + (lane >> 2);
#pragma unroll
        for (int jj = 0; jj < 4; ++jj) {
            int col = n0 + wn * 32 + jj * 8 + (lane & 3) * 2;
            float* d = acc[i * 4 + jj];
            *(float2*)&C[(size_t)row * ldc + col]       = make_float2(d[0], d[1]);
            *(float2*)&C[(size_t)(row + 8) * ldc + col] = make_float2(d[2], d[3]);
        }
    }
}

// ---------------------------------------------------------------------------
// F(4,3) weight transform, all 4 convs in one launch
// ---------------------------------------------------------------------------
__global__ void prep_wU43(const float* __restrict__ Wq, const float* __restrict__ Wk,
                          const float* __restrict__ Wv, const float* __restrict__ Wo)
{
    int g = blockIdx.x * 256 + threadIdx.x;
    int conv = g >> 17;
    int r = g & 131071;
    int co = r >> 8, ci = (r & 255) * 2;
    const float* W = (conv == 0) ? Wq : (conv == 1) ? Wk : (conv == 2) ? Wv : Wo;
    const float* w = W + (size_t)co * 4608 + ci * 9;
    const float c6 = 1.f / 6.f, c12 = 1.f / 12.f, c24 = 1.f / 24.f;
    float TA[6][3], TB[6][3];
#pragma unroll
    for (int k = 0; k < 3; ++k) {
        float a = w[k], b = w[3 + k], c = w[6 + k];
        TA[0][k] = 0.25f * a;
        TA[1][k] = -c6 * (a + b + c);
        TA[2][k] = -c6 * (a - b + c);
        TA[3][k] = c24 * a + c12 * b + c6 * c;
        TA[4][k] = c24 * a - c12 * b + c6 * c;
        TA[5][k] = c;
        float a1 = w[9 + k], b1 = w[12 + k], c1 = w[15 + k];
        TB[0][k] = 0.25f * a1;
        TB[1][k] = -c6 * (a1 + b1 + c1);
        TB[2][k] = -c6 * (a1 - b1 + c1);
        TB[3][k] = c24 * a1 + c12 * b1 + c6 * c1;
        TB[4][k] = c24 * a1 - c12 * b1 + c6 * c1;
        TB[5][k] = c1;
    }
#pragma unroll
    for (int i = 0; i < 6; ++i) {
        float a = TA[i][0], b = TA[i][1], c = TA[i][2];
        float uA[6] = {0.25f * a, -c6 * (a + b + c), -c6 * (a - b + c),
                       c24 * a + c12 * b + c6 * c, c24 * a - c12 * b + c6 * c, c};
        float a1 = TB[i][0], b1 = TB[i][1], c1 = TB[i][2];
        float uB[6] = {0.25f * a1, -c6 * (a1 + b1 + c1), -c6 * (a1 - b1 + c1),
                       c24 * a1 + c12 * b1 + c6 * c1, c24 * a1 - c12 * b1 + c6 * c1, c1};
#pragma unroll
        for (int j = 0; j < 6; ++j) {
            size_t o = ((size_t)(conv * 36 + i * 6 + j) * 512 + co) * 512 + ci;
            uint32_t hp, lp;
            split2(uA[j], uB[j], hp, lp);
            *(uint32_t*)&g_Uh[o] = hp;
            *(uint32_t*)&g_Ul[o] = lp;
        }
    }
}

// ---------------------------------------------------------------------------
// fused transpose + F(4,3) input transform for q/k/v
// ---------------------------------------------------------------------------
#define XF_SMEM (256 * 65 * 4)
__global__ void wino_in_qkv_f(const float* __restrict__ q, const float* __restrict__ k,
                              const float* __restrict__ v)
{
    extern __shared__ float sx[];     // [pix][ci] stride 65
    int cig = blockIdx.x;
    int img = blockIdx.y;
    int z   = blockIdx.z;
    int tid = threadIdx.x;
    const float* base = (z == 0) ? q : (z == 1) ? k : v;
    const float* src = base + (size_t)img * 131072 + (size_t)cig * 64 * 256;
    for (int r = 0; r < 64; ++r)
        sx[tid * 65 + r] = src[(size_t)r * 256 + tid];
    __syncthreads();

#pragma unroll
    for (int item2 = 0; item2 < 2; ++item2) {
        int item = item2 * 256 + tid;
        int mloc = item >> 5, cip = item & 31;
        int ty = mloc >> 1, tx = mloc & 1;
        int y0 = 4 * ty - 1, x0 = 4 * tx - 1;
        int cb = 2 * cip;
        int m = img * 16 + mloc;
        int ci = cig * 64 + cb;

        float2 T[6][6];
#pragma unroll
        for (int c = 0; c < 6; ++c) {
            int x = x0 + c;
            float2 X[6];
#pragma unroll
            for (int r = 0; r < 6; ++r) {
                int y = y0 + r;
                bool ok = ((unsigned)y < 32u) && ((unsigned)x < 8u);
                if (ok) {
                    int pix = y * 8 + x;
                    X[r] = make_float2(sx[pix * 65 + cb], sx[pix * 65 + cb + 1]);
                } else X[r] = make_float2(0.f, 0.f);
            }
            T[0][c] = make_float2(4.f*X[0].x - 5.f*X[2].x + X[4].x,
                                  4.f*X[0].y - 5.f*X[2].y + X[4].y);
            T[1][c] = make_float2(-4.f*X[1].x - 4.f*X[2].x + X[3].x + X[4].x,
                                  -4.f*X[1].y - 4.f*X[2].y + X[3].y + X[4].y);
            T[2][c] = make_float2( 4.f*X[1].x - 4.f*X[2].x - X[3].x + X[4].x,
                                   4.f*X[1].y - 4.f*X[2].y - X[3].y + X[4].y);
            T[3][c] = make_float2(-2.f*X[1].x - X[2].x + 2.f*X[3].x + X[4].x,
                                  -2.f*X[1].y - X[2].y + 2.f*X[3].y + X[4].y);
            T[4][c] = make_float2( 2.f*X[1].x - X[2].x - 2.f*X[3].x + X[4].x,
                                   2.f*X[1].y - X[2].y - 2.f*X[3].y + X[4].y);
            T[5][c] = make_float2( 4.f*X[1].x - 5.f*X[3].x + X[5].x,
                                   4.f*X[1].y - 5.f*X[3].y + X[5].y);
        }
#pragma unroll
        for (int i = 0; i < 6; ++i) {
            float2 t0 = T[i][0], t1 = T[i][1], t2 = T[i][2];
            float2 t3 = T[i][3], t4 = T[i][4], t5 = T[i][5];
            float2 d[6];
            d[0] = make_float2(4.f*t0.x - 5.f*t2.x + t4.x, 4.f*t0.y - 5.f*t2.y + t4.y);
            d[1] = make_float2(-4.f*t1.x - 4.f*t2.x + t3.x + t4.x,
                               -4.f*t1.y - 4.f*t2.y + t3.y + t4.y);
            d[2] = make_float2( 4.f*t1.x - 4.f*t2.x - t3.x + t4.x,
                                4.f*t1.y - 4.f*t2.y - t3.y + t4.y);
            d[3] = make_float2(-2.f*t1.x - t2.x + 2.f*t3.x + t4.x,
                               -2.f*t1.y - t2.y + 2.f*t3.y + t4.y);
            d[4] = make_float2( 2.f*t1.x - t2.x - 2.f*t3.x + t4.x,
                                2.f*t1.y - t2.y - 2.f*t3.y + t4.y);
            d[5] = make_float2( 4.f*t1.x - 5.f*t3.x + t5.x,
                                4.f*t1.y - 5.f*t3.y + t5.y);
#pragma unroll
            for (int j = 0; j < 6; ++j) {
                size_t o = ((size_t)(z * 36 + i * 6 + j) * 512 + m) * 512 + ci;
                uint32_t hp, lp;
                split2(d[j].x, d[j].y, hp, lp);
                *(uint32_t*)&g_Vh[o] = hp;
                *(uint32_t*)&g_Vl[o] = lp;
            }
        }
    }
}

// ---------------------------------------------------------------------------
// F(4,3) input transform from g_saf (conv_o path)
// ---------------------------------------------------------------------------
__global__ void wino_in_o43()
{
    int e = blockIdx.x * 256 + threadIdx.x;
    int m = e >> 8, ci = (e & 255) * 2;
    int img = m >> 7, mr = m & 127;
    int ty = mr >> 6, tx = mr & 63;
    const float* src = g_saf + (size_t)img * 1048576 + ci;
    int y0 = 4 * ty - 1, x0 = 4 * tx - 1;
    float2 T[6][6];
#pragma unroll
    for (int c = 0; c < 6; ++c) {
        int x = x0 + c;
        float2 X[6];
#pragma unroll
        for (int r = 0; r < 6; ++r) {
            int y = y0 + r;
            bool ok = ((unsigned)y < 8u) && ((unsigned)x < 256u);
            X[r] = ok ? *(const float2*)&src[(size_t)(y * 256 + x) * 512]
                      : make_float2(0.f, 0.f);
        }
        T[0][c] = make_float2(4.f*X[0].x - 5.f*X[2].x + X[4].x,
                              4.f*X[0].y - 5.f*X[2].y + X[4].y);
        T[1][c] = make_float2(-4.f*X[1].x - 4.f*X[2].x + X[3].x + X[4].x,
                              -4.f*X[1].y - 4.f*X[2].y + X[3].y + X[4].y);
        T[2][c] = make_float2( 4.f*X[1].x - 4.f*X[2].x - X[3].x + X[4].x,
                               4.f*X[1].y - 4.f*X[2].y - X[3].y + X[4].y);
        T[3][c] = make_float2(-2.f*X[1].x - X[2].x + 2.f*X[3].x + X[4].x,
                              -2.f*X[1].y - X[2].y + 2.f*X[3].y + X[4].y);
        T[4][c] = make_float2( 2.f*X[1].x - X[2].x - 2.f*X[3].x + X[4].x,
                               2.f*X[1].y - X[2].y - 2.f*X[3].y + X[4].y);
        T[5][c] = make_float2( 4.f*X[1].x - 5.f*X[3].x + X[5].x,
                               4.f*X[1].y - 5.f*X[3].y + X[5].y);
    }
#pragma unroll
    for (int i = 0; i < 6; ++i) {
        float2 t0 = T[i][0], t1 = T[i][1], t2 = T[i][2];
        float2 t3 = T[i][3], t4 = T[i][4], t5 = T[i][5];
        float2 d[6];
        d[0] = make_float2(4.f*t0.x - 5.f*t2.x + t4.x, 4.f*t0.y - 5.f*t2.y + t4.y);
        d[1] = make_float2(-4.f*t1.x - 4.f*t2.x + t3.x + t4.x,
                           -4.f*t1.y - 4.f*t2.y + t3.y + t4.y);
        d[2] = make_float2( 4.f*t1.x - 4.f*t2.x - t3.x + t4.x,
                            4.f*t1.y - 4.f*t2.y - t3.y + t4.y);
        d[3] = make_float2(-2.f*t1.x - t2.x + 2.f*t3.x + t4.x,
                           -2.f*t1.y - t2.y + 2.f*t3.y + t4.y);
        d[4] = make_float2( 2.f*t1.x - t2.x - 2.f*t3.x + t4.x,
                            2.f*t1.y - t2.y - 2.f*t3.y + t4.y);
        d[5] = make_float2( 4.f*t1.x - 5.f*t3.x + t5.x,
                            4.f*t1.y - 5.f*t3.y + t5.y);
#pragma unroll
        for (int j = 0; j < 6; ++j) {
            size_t o = ((size_t)(i * 6 + j) * 512 + m) * 512 + ci;
            uint32_t hp, lp;
            split2(d[j].x, d[j].y, hp, lp);
            *(uint32_t*)&g_Vh[o] = hp;
            *(uint32_t*)&g_Vl[o] = lp;
        }
    }
}

// ---------------------------------------------------------------------------
// Winograd GEMM: per plane, C[co][tile] = U[co][ci] . V[tile][ci]^T
// ---------------------------------------------------------------------------
__global__ __launch_bounds__(256, 2) void gemm_wino(int ubase)
{
    int zp = blockIdx.z;
    gemm_mb(g_Uh + (size_t)(ubase + zp) * PSZ, g_Ul + (size_t)(ubase + zp) * PSZ,
            g_Vh + (size_t)zp * PSZ, g_Vl + (size_t)zp * PSZ,
            512, 16, g_M + (size_t)zp * PSZ, 512);
}

// ---------------------------------------------------------------------------
// streaming F(4,3) inverse over an m-pair: accumulate S[4][6] row by row
// ---------------------------------------------------------------------------
__device__ __forceinline__ void wino43_stream_S(const float* __restrict__ Mbase,
                                                float2 (&S)[4][6])
{
#pragma unroll
    for (int i = 0; i < 4; ++i)
#pragma unroll
        for (int c = 0; c < 6; ++c) S[i][c] = make_float2(0.f, 0.f);
#pragma unroll
    for (int r = 0; r < 6; ++r) {
#pragma unroll
        for (int c = 0; c < 6; ++c) {
            float2 mv = *(const float2*)&Mbase[(size_t)(r * 6 + c) * PSZ];
            if (r == 0) {
                S[0][c].x += mv.x; S[0][c].y += mv.y;
            } else if (r == 5) {
                S[3][c].x += mv.x; S[3][c].y += mv.y;
            } else {
                S[0][c].x += mv.x; S[0][c].y += mv.y;
                float w1 = (r == 1) ? 1.f : (r == 2) ? -1.f : (r == 3) ? 2.f : -2.f;
                float w2 = (r <= 2) ? ((r == 2) ? 1.f : 1.f) : 4.f;
                float w3 = (r == 1) ? 1.f : (r == 2) ? -1.f : (r == 3) ? 8.f : -8.f;
                S[1][c].x += w1 * mv.x; S[1][c].y += w1 * mv.y;
                S[2][c].x += w2 * mv.x; S[2][c].y += w2 * mv.y;
                S[3][c].x += w3 * mv.x; S[3][c].y += w3 * mv.y;
            }
        }
    }
}

__device__ __forceinline__ void wino43_inv_row(const float2 (&S)[4][6], int i,
                                               float (&Yx)[4], float (&Yy)[4])
{
    float2 s0 = S[i][0], s1 = S[i][1], s2 = S[i][2];
    float2 s3 = S[i][3], s4 = S[i][4], s5 = S[i][5];
    Yx[0] = s0.x + s1.x + s2.x + s3.x + s4.x;
    Yx[1] = s1.x - s2.x + 2.f * s3.x - 2.f * s4.x;
    Yx[2] = s1.x + s2.x + 4.f * s3.x + 4.f * s4.x;
    Yx[3] = s1.x - s2.x + 8.f * s3.x - 8.f * s4.x + s5.x;
    Yy[0] = s0.y + s1.y + s2.y + s3.y + s4.y;
    Yy[1] = s1.y - s2.y + 2.f * s3.y - 2.f * s4.y;
    Yy[2] = s1.y + s2.y + 4.f * s3.y + 4.f * s4.y;
    Yy[3] = s1.y - s2.y + 8.f * s3.y - 8.f * s4.y + s5.y;
}

// qkv inverse, m-pair vectorized; z<2: fused remap -> Q/K; z=2: fp32 y2
__global__ void wino_out_y43v(const float* __restrict__ bq, const float* __restrict__ bk,
                              const float* __restrict__ bv)
{
    int blk = blockIdx.x;          // 1536 = 3z * 512co
    int z = blk >> 9;
    int co = blk & 511;
    int tid = threadIdx.x;
    int m = tid * 2;               // pair (m, m+1)
    const float* bias = (z == 0) ? bq : (z == 1) ? bk : bv;
    const float* Mbase = g_M + (size_t)(z * 36) * PSZ + co * 512 + m;

    float2 S[4][6];
    wino43_stream_S(Mbase, S);

    float b = bias[co];
    int img = m >> 4;
    int ty = (m & 15) >> 1;        // same for both halves of the pair
    if (z == 2) {
        float* dst = g_y2 + ((size_t)img * 512 + co) * 256 + 32 * ty;
#pragma unroll
        for (int i = 0; i < 4; ++i) {
            float Yx[4], Yy[4];
            wino43_inv_row(S, i, Yx, Yy);
            *(float4*)&dst[8 * i]     = make_float4(Yx[0] + b, Yx[1] + b, Yx[2] + b, Yx[3] + b);
            *(float4*)&dst[8 * i + 4] = make_float4(Yy[0] + b, Yy[1] + b, Yy[2] + b, Yy[3] + b);
        }
    } else {
        __nv_bfloat16* oh = z ? g_Kh : g_Qh;
        __nv_bfloat16* ol = z ? g_Kl : g_Ql;
        int hh = img >> 2;
        int nn = (img & 3) * 8 + (co >> 6);
        int d  = (co & 63) * 8 + ty;
        size_t rowo = ((size_t)nn * 512 + d) * 256;
#pragma unroll
        for (int i = 0; i < 4; ++i) {
            float Yx[4], Yy[4];
            wino43_inv_row(S, i, Yx, Yy);
            int cbase = hh * 32 + 8 * i;
            uint32_t h0, l0, h1, l1, h2, l2, h3, l3;
            split2(Yx[0] + b, Yx[1] + b, h0, l0);
            split2(Yx[2] + b, Yx[3] + b, h1, l1);
            split2(Yy[0] + b, Yy[1] + b, h2, l2);
            split2(Yy[2] + b, Yy[3] + b, h3, l3);
            *(uint4*)&oh[rowo + cbase] = make_uint4(h0, h1, h2, h3);
            *(uint4*)&ol[rowo + cbase] = make_uint4(l0, l1, l2, l3);
        }
    }
}

__global__ void wino_out_o43v(const float* __restrict__ bo, float* __restrict__ out)
{
    int co = blockIdx.x;           // 512
    int tid = threadIdx.x;
    int m = tid * 2;
    const float* Mbase = g_M + (size_t)co * 512 + m;

    float2 S[4][6];
    wino43_stream_S(Mbase, S);

    float b = bo[co];
    int img = m >> 7;
    int ty = (m & 127) >> 6;
    int tx = m & 63;
    float* dst = out + ((size_t)img * 512 + co) * 2048 + (4 * ty) * 256 + 4 * tx;
#pragma unroll
    for (int i = 0; i < 4; ++i) {
        float Yx[4], Yy[4];
        wino43_inv_row(S, i, Yx, Yy);
        *(float4*)&dst[256 * i]     = make_float4(Yx[0] + b, Yx[1] + b, Yx[2] + b, Yx[3] + b);
        *(float4*)&dst[256 * i + 4] = make_float4(Yy[0] + b, Yy[1] + b, Yy[2] + b, Yy[3] + b);
    }
}

// ---------------------------------------------------------------------------
// smem-tiled V transpose: g_y2 -> Vt bf16 hi/lo [n][c][dk]
// ---------------------------------------------------------------------------
#define VT_SMEM (64 * 257 * 4)
__global__ void remap_V_t()
{
    extern __shared__ float sy[];         // [co2local][pix] stride 257
    int img2 = blockIdx.x & 31;
    int nlo  = blockIdx.x >> 5;
    int tid = threadIdx.x;
    const float* src = g_y2 + (size_t)img2 * 131072 + (size_t)nlo * 64 * 256;
    for (int rw = 0; rw < 64; ++rw)
        sy[rw * 257 + tid] = src[(size_t)rw * 256 + tid];
    __syncthreads();

    int h = img2 >> 2, nhi = img2 & 3;
    int n = nhi * 8 + nlo;
    int dkhi = tid & 63, rg = tid >> 6;
#pragma unroll
    for (int it = 0; it < 8; ++it) {
        int r = it * 4 + rg;
        int c = h * 32 + r;
        uint32_t hp[4], lp[4];
#pragma unroll
        for (int qd = 0; qd < 4; ++qd) {
            float v0 = sy[dkhi * 257 + (2 * qd) * 32 + r];
            float v1 = sy[dkhi * 257 + (2 * qd + 1) * 32 + r];
            split2(v0, v1, hp[qd], lp[qd]);
        }
        size_t o = ((size_t)n * 256 + c) * 512 + dkhi * 8;
        *(uint4*)&g_Vth[o] = make_uint4(hp[0], hp[1], hp[2], hp[3]);
        *(uint4*)&g_Vtl[o] = make_uint4(lp[0], lp[1], lp[2], lp[3]);
    }
}

// ---------------------------------------------------------------------------
// attention GEMMs
// ---------------------------------------------------------------------------
__global__ __launch_bounds__(256, 2) void gemm_scores(float* __restrict__ attn)
{
    int nb = blockIdx.z;
    gemm_mb(g_Qh + (size_t)nb * 131072, g_Ql + (size_t)nb * 131072,
            g_Kh + (size_t)nb * 131072, g_Kl + (size_t)nb * 131072,
            256, 8, attn + (size_t)nb * 262144, 512);
}

// gemm_nnout with fused saf-scatter epilogue
__global__ __launch_bounds__(256, 2) void gemm_nnout_saf()
{
    extern __shared__ char smem[];
    uint32_t sb = smem_u32(smem);
    int tid = threadIdx.x, wid = tid >> 5, lane = tid & 31;
    int nb = blockIdx.z;
    int m0 = blockIdx.y * 128, n0 = blockIdx.x * 128;
    int wm = wid & 1, wn = wid >> 1;

    PipeCtx P;
    pipe_init(P, sb, tid,
              g_ath + (size_t)nb * 262144, g_atl + (size_t)nb * 262144,
              g_Vth + (size_t)nb * 131072, g_Vtl + (size_t)nb * 131072,
              m0, n0, 512);

    float acc[16][4];
#pragma unroll
    for (int i = 0; i < 16; ++i)
#pragma unroll
        for (int j = 0; j < 4; ++j) acc[i][j] = 0.f;

    pipe_mainloop(P, 16, acc);

    __syncthreads();
    float* sf = (float*)smem;
#pragma unroll
    for (int i = 0; i < 4; ++i) {
        int row = wm * 64 + i * 16 + (lane >> 2);
#pragma unroll
        for (int jj = 0; jj < 4; ++jj) {
            int col = wn * 32 + jj * 8 + (lane & 3) * 2;
            float* d = acc[i * 4 + jj];
            *(float2*)&sf[row * 130 + col]       = make_float2(d[0], d[1]);
            *(float2*)&sf[(row + 8) * 130 + col] = make_float2(d[2], d[3]);
        }
    }
    __syncthreads();

    int b = nb >> 3, s = nb & 7;
    int rr = tid & 31, rg = tid >> 5;
    int hh0 = n0 >> 5;
    float* sab = g_saf + (size_t)b * 1048576;
#pragma unroll
    for (int it = 0; it < 16; ++it) {
        int row = it * 8 + rg;
        int qd = m0 + row;
        int p = s * 256 + (qd >> 4) * 8 + ((qd >> 1) & 7);
        int d2 = (qd & 1) * 256 + rr * 8 + hh0;
        float4 v = make_float4(sf[row * 130 + rr],       sf[row * 130 + 32 + rr],
                               sf[row * 130 + 64 + rr],  sf[row * 130 + 96 + rr]);
        *(float4*)&sab[(size_t)p * 512 + d2] = v;
    }
}

// ---------------------------------------------------------------------------
// softmax: one 512-wide row per 128-thread block, float4 path
// ---------------------------------------------------------------------------
__global__ void softmax_rows(float* __restrict__ attn)
{
    size_t base = (size_t)blockIdx.x * 512;
    float* p = attn + base;
    int tid = threadIdx.x;                 // 0..127
    int wid = tid >> 5, lane = tid & 31;
    float4 v = *(float4*)&p[tid * 4];
    float m = fmaxf(fmaxf(v.x, v.y), fmaxf(v.z, v.w));
#pragma unroll
    for (int o = 16; o; o >>= 1) m = fmaxf(m, __shfl_xor_sync(~0u, m, o));
    __shared__ float sm[4], ss[4];
    if (lane == 0) sm[wid] = m;
    __syncthreads();
    float M = fmaxf(fmaxf(sm[0], sm[1]), fmaxf(sm[2], sm[3]));
    float4 e = make_float4(expf(v.x - M), expf(v.y - M), expf(v.z - M), expf(v.w - M));
    float s = e.x + e.y + e.z + e.w;
#pragma unroll
    for (int o = 16; o; o >>= 1) s += __shfl_xor_sync(~0u, s, o);
    if (lane == 0) ss[wid] = s;
    __syncthreads();
    float inv = 1.f / (ss[0] + ss[1] + ss[2] + ss[3]);
    float4 a = make_float4(e.x * inv, e.y * inv, e.z * inv, e.w * inv);
    *(float4*)&p[tid * 4] = a;
    uint32_t h0, l0, h1, l1;
    split2(a.x, a.y, h0, l0);
    split2(a.z, a.w, h1, l1);
    *(uint2*)&g_ath[base + tid * 4] = make_uint2(h0, h1);
    *(uint2*)&g_atl[base + tid * 4] = make_uint2(l0, l1);
}

// ---------------------------------------------------------------------------
extern "C" void kernel_launch(void* const* d_in, const int* in_sizes, int n_in,
                              void* d_out, int out_size)
{
    const float* q  = (const float*)d_in[0];
    const float* k  = (const float*)d_in[1];
    const float* v  = (const float*)d_in[2];
    const float* Wq = (const float*)d_in[3];
    const float* bq = (const float*)d_in[4];
    const float* Wk = (const float*)d_in[5];
    const float* bk = (const float*)d_in[6];
    const float* Wv = (const float*)d_in[7];
    const float* bv = (const float*)d_in[8];
    const float* Wo = (const float*)d_in[9];
    const float* bo = (const float*)d_in[10];

    float* y_out    = (float*)d_out;            // (4,512,8,32,8) = 4194304
    float* attn_out = y_out + NELEM;            // (1,32,512,512) = 8388608

    cudaFuncSetAttribute(gemm_wino,      cudaFuncAttributeMaxDynamicSharedMemorySize, SMEM_BYTES);
    cudaFuncSetAttribute(gemm_scores,    cudaFuncAttributeMaxDynamicSharedMemorySize, SMEM_BYTES);
    cudaFuncSetAttribute(gemm_nnout_saf, cudaFuncAttributeMaxDynamicSharedMemorySize, SMEM_BYTES);
    cudaFuncSetAttribute(wino_in_qkv_f,  cudaFuncAttributeMaxDynamicSharedMemorySize, XF_SMEM);
    cudaFuncSetAttribute(remap_V_t,      cudaFuncAttributeMaxDynamicSharedMemorySize, VT_SMEM);

    // launch order: index 3 = wino_out_y43v (verify the vectorization)
    prep_wU43<<<2048, 256>>>(Wq, Wk, Wv, Wo);                        // 0
    wino_in_qkv_f<<<dim3(8, 32, 3), 256, XF_SMEM>>>(q, k, v);        // 1
    gemm_wino<<<dim3(4, 4, 108), 256, SMEM_BYTES>>>(0);              // 2
    wino_out_y43v<<<1536, 256>>>(bq, bk, bv);                        // 3  <- profiled
    remap_V_t<<<256, 256, VT_SMEM>>>();                              // 4
    gemm_scores<<<dim3(4, 4, 32), 256, SMEM_BYTES>>>(attn_out);      // 5
    softmax_rows<<<32 * 512, 128>>>(attn_out);                       // 6
    gemm_nnout_saf<<<dim3(2, 4, 32), 256, SMEM_BYTES>>>();           // 7
    wino_in_o43<<<512, 256>>>();                                     // 8
    gemm_wino<<<dim3(4, 4, 36), 256, SMEM_BYTES>>>(108);             // 9
    wino_out_o43v<<<512, 256>>>(bo, y_out);                          // 10
}